// round 3
// baseline (speedup 1.0000x reference)
#include <cuda_runtime.h>

// RandomShiftsAug == integer shifted gather with edge clamp:
//   out[n,c,j,i] = x[n,c, clamp(j+sy-4,0,83), clamp(i+sx-4,0,83)]
//
// The shift is word-granular, so the optimal pattern is scalar, lane-contiguous
// LDG.32 / STG.32: a warp's 32 loads are consecutive addresses (perfectly
// coalesced even at odd word offsets), eliminating the sector-replay blowup
// that capped R1 (strided 16B lanes) and the smem roundtrip that sank R2.
// Pure HBM-bound copy: 130 MB in + 130 MB out.

#define N_   512
#define C_   9
#define H_   84
#define W_   84
#define PAD_ 4

#define SLICE     (H_ * W_)                    // 7056
#define THREADS   256
#define SEGS      ((SLICE + THREADS - 1) / THREADS)   // 28 segments per slice

__global__ __launch_bounds__(THREADS) void random_shift_scalar_kernel(
    const float* __restrict__ x,
    const int*   __restrict__ shift,
    float*       __restrict__ out)
{
    const int bid = blockIdx.x;
    const int nc  = bid / SEGS;            // which (n,c) slice
    const int seg = bid - nc * SEGS;       // which 256-element segment

    const int idx = seg * THREADS + threadIdx.x;   // element within slice
    if (idx >= SLICE) return;

    const int n  = nc / C_;
    const int sx = __ldg(&shift[2 * n + 0]) - PAD_;   // [-4, 4]
    const int sy = __ldg(&shift[2 * n + 1]) - PAD_;

    const int j = idx / W_;                // output row
    const int i = idx - j * W_;            // output col

    const int srcy = min(max(j + sy, 0), H_ - 1);
    const int srcx = min(max(i + sx, 0), W_ - 1);

    const long base = (long)nc * SLICE;
    float v = __ldcs(&x[base + srcy * W_ + srcx]);
    __stcs(&out[base + idx], v);
}

extern "C" void kernel_launch(void* const* d_in, const int* in_sizes, int n_in,
                              void* d_out, int out_size)
{
    const float* x     = (const float*)d_in[0];
    const int*   shift = (const int*)  d_in[1];
    float* out = (float*)d_out;

    random_shift_scalar_kernel<<<N_ * C_ * SEGS, THREADS>>>(x, shift, out);
}

// round 4
// speedup vs baseline: 2.3657x; 2.3657x over previous
#include <cuda_runtime.h>

// RandomShiftsAug == integer shifted gather with edge clamp:
//   out[n,c,j,i] = x[n,c, clamp(j+sy-4,0,83), clamp(i+sx-4,0,83)]
//
// R1 (float4, strided lanes): good MLP, terrible sectoring (16 lines/warp-LDG).
// R3 (scalar, 1 elem/thread): perfect sectoring, MLP=1 -> latency-bound.
// R4: scalar lane-contiguous access AND 28 independent loads per thread.
//   Block = one (n,c) slice; 252 threads = 3 rows x 84 cols; thread (j0,i)
//   covers rows j0+3k. Column clamp hoisted out of the loop; loads batched
//   before stores so the warp keeps ~28 requests in flight.

#define N_   512
#define C_   9
#define H_   84
#define W_   84
#define PAD_ 4

#define SLICE    (H_ * W_)     // 7056
#define THREADS  252           // 3 * 84
#define KITER    28            // 84 rows / 3

__global__ __launch_bounds__(THREADS) void random_shift_mlp_kernel(
    const float* __restrict__ x,
    const int*   __restrict__ shift,
    float*       __restrict__ out)
{
    const int nc  = blockIdx.x;          // (n*C + c)
    const int n   = nc / C_;
    const int tid = threadIdx.x;

    const int i  = tid % W_;             // column, 0..83
    const int j0 = tid / W_;             // starting row, 0..2

    const int sx = __ldg(&shift[2 * n + 0]) - PAD_;   // [-4, 4]
    const int sy = __ldg(&shift[2 * n + 1]) - PAD_;

    const int srcx = min(max(i + sx, 0), W_ - 1);     // hoisted: column fixed

    const float* __restrict__ src = x   + (long)nc * SLICE + srcx;
    float*       __restrict__ dst = out + (long)nc * SLICE + i;

    const int jy = j0 + sy;              // unclamped source row at k=0

    float v[KITER];
    #pragma unroll
    for (int k = 0; k < KITER; k++) {
        int srcy = min(max(jy + 3 * k, 0), H_ - 1);
        v[k] = __ldcs(src + srcy * W_);
    }

    #pragma unroll
    for (int k = 0; k < KITER; k++) {
        __stcs(dst + (j0 + 3 * k) * W_, v[k]);
    }
}

extern "C" void kernel_launch(void* const* d_in, const int* in_sizes, int n_in,
                              void* d_out, int out_size)
{
    const float* x     = (const float*)d_in[0];
    const int*   shift = (const int*)  d_in[1];
    float* out = (float*)d_out;

    random_shift_mlp_kernel<<<N_ * C_, THREADS>>>(x, shift, out);
}